// round 2
// baseline (speedup 1.0000x reference)
#include <cuda_runtime.h>
#include <cuda_bf16.h>

#define NN 50000
#define NE 1600000
#define D  64
#define NLAYER 4
#define BN_EPS 1e-5f

// ---------------- scratch (device globals; no allocs allowed) ----------------
__device__ __align__(16) float g_h[NN * D];
__device__ __align__(16) float g_P[NN * D];
__device__ __align__(16) float g_Q[NN * D];
__device__ __align__(16) float g_aggr[NN * D];
__device__ __align__(16) float g_zn[NN * D];
__device__ __align__(16) float g_zn2[NN * D];
__device__ __align__(16) float g_z2[(size_t)NE * D];      // 409.6 MB edge scratch
// [0:64) sum  [64:128) sumsq  [128:192) scale  [192:256) shift
__device__ __align__(16) float g_stats[256];

// ---------------- helpers ----------------
__device__ __forceinline__ void gemm_tile_128(const float* __restrict__ A,
                                              const float* __restrict__ W,
                                              float acc[8][4], int tx, int ty) {
    // A: 128x64 (smem), W: 64x64 (smem). Thread covers rows 8*ty..+7, cols 4*tx..+3
#pragma unroll 4
    for (int k = 0; k < 64; k++) {
        float4 bv = *(const float4*)(W + k * 64 + tx * 4);
#pragma unroll
        for (int i = 0; i < 8; i++) {
            float a = A[(ty * 8 + i) * 64 + k];
            acc[i][0] = fmaf(a, bv.x, acc[i][0]);
            acc[i][1] = fmaf(a, bv.y, acc[i][1]);
            acc[i][2] = fmaf(a, bv.z, acc[i][2]);
            acc[i][3] = fmaf(a, bv.w, acc[i][3]);
        }
    }
}

// reduce 4 col-sums + 4 col-sumsqs (cols 4*lane..+3) across 16 slots, atomically into g_stats
__device__ __forceinline__ void reduce_stats_8(float* rb, const float* vals, int lane, int slot) {
#pragma unroll
    for (int v = 0; v < 8; v++) {
        __syncthreads();
        rb[slot * 17 + lane] = vals[v];
        __syncthreads();
        if (slot == 0) {
            float t = 0.f;
#pragma unroll
            for (int k = 0; k < 16; k++) t += rb[k * 17 + lane];
            atomicAdd(&g_stats[(v < 4 ? 0 : 64) + lane * 4 + (v & 3)], t);
        }
    }
}

// ---------------- kernels ----------------

// h = x @ lin_in_W + lin_in_b ; also zero stats accumulators once
__global__ void k_lin_in(const float* __restrict__ x, const float* __restrict__ W,
                         const float* __restrict__ b) {
    __shared__ __align__(16) float Ws[6 * 64];
    __shared__ float bs[64];
    int tid = threadIdx.x;
    for (int i = tid; i < 384; i += 256) Ws[i] = W[i];
    if (tid < 64) bs[tid] = b[tid];
    if (blockIdx.x == 0 && tid < 128) g_stats[tid] = 0.f;
    __syncthreads();
    int c = tid & 63;
    for (int n = blockIdx.x * 4 + (tid >> 6); n < NN; n += gridDim.x * 4) {
        float acc = bs[c];
#pragma unroll
        for (int k = 0; k < 6; k++) acc = fmaf(x[n * 6 + k], Ws[k * 64 + c], acc);
        g_h[n * 64 + c] = acc;
    }
}

// P = h @ W1[:64], Q = h @ W1[64:128]; zero aggr for this node tile
__global__ void k_node_PQ(const float* __restrict__ W1) {
    __shared__ __align__(16) float Ws[4096];
    __shared__ __align__(16) float hs[8192];
    int tid = threadIdx.x, tx = tid & 15, ty = tid >> 4;
    int row0 = blockIdx.x * 128;

    for (int i = tid; i < 2048; i += 256) {
        int idx = row0 * 64 + i * 4;
        float4 z = make_float4(0, 0, 0, 0);
        if (idx < NN * 64) { *(float4*)(g_aggr + idx) = z; z = *(const float4*)(g_h + idx); }
        *(float4*)(hs + i * 4) = z;
    }
    for (int i = tid; i < 1024; i += 256) *(float4*)(Ws + i * 4) = *(const float4*)(W1 + i * 4);
    __syncthreads();

    float acc[8][4];
#pragma unroll
    for (int i = 0; i < 8; i++) { acc[i][0]=acc[i][1]=acc[i][2]=acc[i][3]=0.f; }
    gemm_tile_128(hs, Ws, acc, tx, ty);
#pragma unroll
    for (int i = 0; i < 8; i++) {
        int r = row0 + ty * 8 + i;
        if (r < NN) *(float4*)(g_P + r * 64 + tx * 4) =
            make_float4(acc[i][0], acc[i][1], acc[i][2], acc[i][3]);
    }
    __syncthreads();
    for (int i = tid; i < 1024; i += 256) *(float4*)(Ws + i * 4) = *(const float4*)(W1 + 4096 + i * 4);
    __syncthreads();
#pragma unroll
    for (int i = 0; i < 8; i++) { acc[i][0]=acc[i][1]=acc[i][2]=acc[i][3]=0.f; }
    gemm_tile_128(hs, Ws, acc, tx, ty);
#pragma unroll
    for (int i = 0; i < 8; i++) {
        int r = row0 + ty * 8 + i;
        if (r < NN) *(float4*)(g_Q + r * 64 + tx * 4) =
            make_float4(acc[i][0], acc[i][1], acc[i][2], acc[i][3]);
    }
}

// pass 1 over edges: z1 = P[dst]+Q[src]+w1c*ea -> accumulate col sums / sumsqs
__global__ void k_edge_z1_stats(const int* __restrict__ EI, const float* __restrict__ EA,
                                const float* __restrict__ W1) {
    __shared__ __align__(16) float wc[64];
    __shared__ float rb[16 * 17];
    int tid = threadIdx.x, lane = tid & 15, slot = tid >> 4;
    if (tid < 64) wc[tid] = W1[128 * 64 + tid];
    __syncthreads();
    float4 wcv = *(const float4*)(wc + lane * 4);
    float vals[8] = {0, 0, 0, 0, 0, 0, 0, 0};
    for (int e = blockIdx.x * 16 + slot; e < NE; e += gridDim.x * 16) {
        int d = EI[NE + e], s = EI[e];
        float ea = EA[e];
        float4 p = *(const float4*)(g_P + (size_t)d * 64 + lane * 4);
        float4 q = *(const float4*)(g_Q + (size_t)s * 64 + lane * 4);
        float z0 = p.x + q.x + wcv.x * ea;
        float z1 = p.y + q.y + wcv.y * ea;
        float z2 = p.z + q.z + wcv.z * ea;
        float z3 = p.w + q.w + wcv.w * ea;
        vals[0] += z0; vals[1] += z1; vals[2] += z2; vals[3] += z3;
        vals[4] += z0 * z0; vals[5] += z1 * z1; vals[6] += z2 * z2; vals[7] += z3 * z3;
    }
    reduce_stats_8(rb, vals, lane, slot);
}

// scale = g*rsqrt(var+eps); shift = be - mu*scale; re-zero accumulators
__global__ void k_finalize(const float* __restrict__ g, const float* __restrict__ be,
                           float invCnt) {
    int c = threadIdx.x;
    float mu = g_stats[c] * invCnt;
    float var = g_stats[64 + c] * invCnt - mu * mu;
    float sc = g[c] * rsqrtf(var + BN_EPS);
    g_stats[128 + c] = sc;
    g_stats[192 + c] = be[c] - mu * sc;
    g_stats[c] = 0.f;
    g_stats[64 + c] = 0.f;
}

// pass 2 over edges: recompute z1, x1=relu(bn), z2 = x1@W2 -> store z2, stats(z2)
__global__ void k_edge_z2(const int* __restrict__ EI, const float* __restrict__ EA,
                          const float* __restrict__ W1, const float* __restrict__ W2) {
    __shared__ __align__(16) float Ws[4096];
    __shared__ __align__(16) float x1s[8192];
    int tid = threadIdx.x, lane = tid & 15, slot = tid >> 4;
    int tx = lane, ty = slot;
    for (int i = tid; i < 1024; i += 256) *(float4*)(Ws + i * 4) = *(const float4*)(W2 + i * 4);
    float4 wcv = *(const float4*)(W1 + 128 * 64 + lane * 4);
    float4 scv = *(const float4*)(g_stats + 128 + lane * 4);
    float4 shv = *(const float4*)(g_stats + 192 + lane * 4);
    float vals[8] = {0, 0, 0, 0, 0, 0, 0, 0};

    for (int tile = blockIdx.x; tile < NE / 128; tile += gridDim.x) {
        size_t base = (size_t)tile * 128;
        __syncthreads();  // protect x1s (and first-iter Ws)
#pragma unroll
        for (int j = 0; j < 8; j++) {
            int el = slot + j * 16;
            size_t e = base + el;
            int d = EI[NE + e], s = EI[e];
            float ea = EA[e];
            float4 p = *(const float4*)(g_P + (size_t)d * 64 + lane * 4);
            float4 q = *(const float4*)(g_Q + (size_t)s * 64 + lane * 4);
            float4 x;
            x.x = fmaxf(fmaf(p.x + q.x + wcv.x * ea, scv.x, shv.x), 0.f);
            x.y = fmaxf(fmaf(p.y + q.y + wcv.y * ea, scv.y, shv.y), 0.f);
            x.z = fmaxf(fmaf(p.z + q.z + wcv.z * ea, scv.z, shv.z), 0.f);
            x.w = fmaxf(fmaf(p.w + q.w + wcv.w * ea, scv.w, shv.w), 0.f);
            *(float4*)(x1s + el * 64 + lane * 4) = x;
        }
        __syncthreads();
        float acc[8][4];
#pragma unroll
        for (int i = 0; i < 8; i++) { acc[i][0]=acc[i][1]=acc[i][2]=acc[i][3]=0.f; }
        gemm_tile_128(x1s, Ws, acc, tx, ty);
#pragma unroll
        for (int i = 0; i < 8; i++) {
            size_t r = base + ty * 8 + i;
            float4 o = make_float4(acc[i][0], acc[i][1], acc[i][2], acc[i][3]);
            *(float4*)(g_z2 + r * 64 + tx * 4) = o;
            vals[0] += o.x; vals[1] += o.y; vals[2] += o.z; vals[3] += o.w;
            vals[4] += o.x * o.x; vals[5] += o.y * o.y;
            vals[6] += o.z * o.z; vals[7] += o.w * o.w;
        }
    }
    __syncthreads();
    reduce_stats_8(x1s, vals, lane, slot);  // reuse x1s as reduction buffer
}

// pass 3 over edges: m = relu(bn(z2)); vectorized scatter-add into aggr[dst]
__global__ void k_edge_scatter(const int* __restrict__ EI) {
    int tid = threadIdx.x, lane = tid & 15;
    float4 scv = *(const float4*)(g_stats + 128 + lane * 4);
    float4 shv = *(const float4*)(g_stats + 192 + lane * 4);
    size_t stride = (size_t)gridDim.x * blockDim.x;
    for (size_t i = (size_t)blockIdx.x * blockDim.x + tid; i < (size_t)NE * 16; i += stride) {
        size_t e = i >> 4;
        float4 z = *(const float4*)(g_z2 + e * 64 + lane * 4);
        float4 m;
        m.x = fmaxf(fmaf(z.x, scv.x, shv.x), 0.f);
        m.y = fmaxf(fmaf(z.y, scv.y, shv.y), 0.f);
        m.z = fmaxf(fmaf(z.z, scv.z, shv.z), 0.f);
        m.w = fmaxf(fmaf(z.w, scv.w, shv.w), 0.f);
        int d = EI[NE + e];
        float* addr = g_aggr + (size_t)d * 64 + lane * 4;
        asm volatile("red.global.add.v4.f32 [%0], {%1,%2,%3,%4};"
                     :: "l"(addr), "f"(m.x), "f"(m.y), "f"(m.z), "f"(m.w) : "memory");
    }
}

// z3 = h @ U1[:64] + aggr @ U1[64:128]; stats(z3)
__global__ void k_node_z3(const float* __restrict__ U1) {
    __shared__ __align__(16) float Ws[4096];
    __shared__ __align__(16) float ins[8192];
    int tid = threadIdx.x, tx = tid & 15, ty = tid >> 4;
    int row0 = blockIdx.x * 128;

    for (int i = tid; i < 1024; i += 256) *(float4*)(Ws + i * 4) = *(const float4*)(U1 + i * 4);
    for (int i = tid; i < 2048; i += 256) {
        int idx = row0 * 64 + i * 4;
        float4 v = (idx < NN * 64) ? *(const float4*)(g_h + idx) : make_float4(0, 0, 0, 0);
        *(float4*)(ins + i * 4) = v;
    }
    __syncthreads();
    float acc[8][4];
#pragma unroll
    for (int i = 0; i < 8; i++) { acc[i][0]=acc[i][1]=acc[i][2]=acc[i][3]=0.f; }
    gemm_tile_128(ins, Ws, acc, tx, ty);
    __syncthreads();
    for (int i = tid; i < 1024; i += 256) *(float4*)(Ws + i * 4) = *(const float4*)(U1 + 4096 + i * 4);
    for (int i = tid; i < 2048; i += 256) {
        int idx = row0 * 64 + i * 4;
        float4 v = (idx < NN * 64) ? *(const float4*)(g_aggr + idx) : make_float4(0, 0, 0, 0);
        *(float4*)(ins + i * 4) = v;
    }
    __syncthreads();
    gemm_tile_128(ins, Ws, acc, tx, ty);

    float vals[8] = {0, 0, 0, 0, 0, 0, 0, 0};
#pragma unroll
    for (int i = 0; i < 8; i++) {
        int r = row0 + ty * 8 + i;
        float4 o = make_float4(acc[i][0], acc[i][1], acc[i][2], acc[i][3]);
        if (r < NN) *(float4*)(g_zn + r * 64 + tx * 4) = o;
        vals[0] += o.x; vals[1] += o.y; vals[2] += o.z; vals[3] += o.w;
        vals[4] += o.x * o.x; vals[5] += o.y * o.y; vals[6] += o.z * o.z; vals[7] += o.w * o.w;
    }
    __syncthreads();
    reduce_stats_8(ins, vals, tx, ty);
}

// z4 = relu(bn(z3)) @ U2; stats(z4)
__global__ void k_node_z4(const float* __restrict__ U2) {
    __shared__ __align__(16) float Ws[4096];
    __shared__ __align__(16) float ins[8192];
    int tid = threadIdx.x, tx = tid & 15, ty = tid >> 4;
    int row0 = blockIdx.x * 128;
    for (int i = tid; i < 1024; i += 256) *(float4*)(Ws + i * 4) = *(const float4*)(U2 + i * 4);
    for (int i = tid; i < 2048; i += 256) {
        int idx = row0 * 64 + i * 4;
        int c = (i * 4) & 63;
        float4 v = make_float4(0, 0, 0, 0);
        if (idx < NN * 64) {
            float4 z = *(const float4*)(g_zn + idx);
            float4 sc = *(const float4*)(g_stats + 128 + c);
            float4 sh = *(const float4*)(g_stats + 192 + c);
            v.x = fmaxf(fmaf(z.x, sc.x, sh.x), 0.f);
            v.y = fmaxf(fmaf(z.y, sc.y, sh.y), 0.f);
            v.z = fmaxf(fmaf(z.z, sc.z, sh.z), 0.f);
            v.w = fmaxf(fmaf(z.w, sc.w, sh.w), 0.f);
        }
        *(float4*)(ins + i * 4) = v;
    }
    __syncthreads();
    float acc[8][4];
#pragma unroll
    for (int i = 0; i < 8; i++) { acc[i][0]=acc[i][1]=acc[i][2]=acc[i][3]=0.f; }
    gemm_tile_128(ins, Ws, acc, tx, ty);

    float vals[8] = {0, 0, 0, 0, 0, 0, 0, 0};
#pragma unroll
    for (int i = 0; i < 8; i++) {
        int r = row0 + ty * 8 + i;
        float4 o = make_float4(acc[i][0], acc[i][1], acc[i][2], acc[i][3]);
        if (r < NN) *(float4*)(g_zn2 + r * 64 + tx * 4) = o;
        vals[0] += o.x; vals[1] += o.y; vals[2] += o.z; vals[3] += o.w;
        vals[4] += o.x * o.x; vals[5] += o.y * o.y; vals[6] += o.z * o.z; vals[7] += o.w * o.w;
    }
    __syncthreads();
    reduce_stats_8(ins, vals, tx, ty);
}

// h += relu(bn(z4))
__global__ void k_node_upd() {
    size_t stride = (size_t)gridDim.x * blockDim.x;
    for (size_t i = (size_t)blockIdx.x * blockDim.x + threadIdx.x; i < (size_t)NN * 16; i += stride) {
        int c = (int)((i & 15) * 4);
        float4 z = *(const float4*)(g_zn2 + i * 4);
        float4 sc = *(const float4*)(g_stats + 128 + c);
        float4 sh = *(const float4*)(g_stats + 192 + c);
        float4 h = *(const float4*)(g_h + i * 4);
        h.x += fmaxf(fmaf(z.x, sc.x, sh.x), 0.f);
        h.y += fmaxf(fmaf(z.y, sc.y, sh.y), 0.f);
        h.z += fmaxf(fmaf(z.z, sc.z, sh.z), 0.f);
        h.w += fmaxf(fmaf(z.w, sc.w, sh.w), 0.f);
        *(float4*)(g_h + i * 4) = h;
    }
}

// out[n] = h[n] . pred_W + pred_b
__global__ void k_pred(const float* __restrict__ Wp, const float* __restrict__ bp,
                       float* __restrict__ out) {
    __shared__ float Wps[64];
    int tid = threadIdx.x;
    if (tid < 64) Wps[tid] = Wp[tid];
    __syncthreads();
    int lane = tid & 31, w = tid >> 5;
    int n = blockIdx.x * 8 + w;
    if (n >= NN) return;
    float2 v = *(const float2*)(g_h + (size_t)n * 64 + lane * 2);
    float p = v.x * Wps[lane * 2] + v.y * Wps[lane * 2 + 1];
#pragma unroll
    for (int off = 16; off; off >>= 1) p += __shfl_xor_sync(0xffffffffu, p, off);
    if (lane == 0) out[n] = p + bp[0];
}

// ---------------- launch ----------------
extern "C" void kernel_launch(void* const* d_in, const int* in_sizes, int n_in,
                              void* d_out, int out_size) {
    const float* x    = (const float*)d_in[0];
    const int*   EI   = (const int*)d_in[1];
    const float* EA   = (const float*)d_in[2];
    const float* linW = (const float*)d_in[3];
    const float* linb = (const float*)d_in[4];
    const float* mW1  = (const float*)d_in[5];
    const float* mg1  = (const float*)d_in[7];
    const float* mbe1 = (const float*)d_in[8];
    const float* mW2  = (const float*)d_in[9];
    const float* mg2  = (const float*)d_in[11];
    const float* mbe2 = (const float*)d_in[12];
    const float* uW1  = (const float*)d_in[13];
    const float* ug1  = (const float*)d_in[15];
    const float* ube1 = (const float*)d_in[16];
    const float* uW2  = (const float*)d_in[17];
    const float* ug2  = (const float*)d_in[19];
    const float* ube2 = (const float*)d_in[20];
    const float* pW   = (const float*)d_in[21];
    const float* pb   = (const float*)d_in[22];
    float* out = (float*)d_out;

    const float invE = 1.0f / (float)NE;
    const float invN = 1.0f / (float)NN;
    const int NODE_TILES = (NN + 127) / 128;  // 391

    k_lin_in<<<1184, 256>>>(x, linW, linb);
    for (int l = 0; l < NLAYER; l++) {
        const float* W1 = mW1 + (size_t)l * 129 * 64;
        const float* W2 = mW2 + (size_t)l * 64 * 64;
        const float* U1 = uW1 + (size_t)l * 128 * 64;
        const float* U2 = uW2 + (size_t)l * 64 * 64;
        k_node_PQ<<<NODE_TILES, 256>>>(W1);
        k_edge_z1_stats<<<1480, 256>>>(EI, EA, W1);
        k_finalize<<<1, 64>>>(mg1 + l * 64, mbe1 + l * 64, invE);
        k_edge_z2<<<1480, 256>>>(EI, EA, W1, W2);
        k_finalize<<<1, 64>>>(mg2 + l * 64, mbe2 + l * 64, invE);
        k_edge_scatter<<<9472, 256>>>(EI);
        k_node_z3<<<NODE_TILES, 256>>>(U1);
        k_finalize<<<1, 64>>>(ug1 + l * 64, ube1 + l * 64, invN);
        k_node_z4<<<NODE_TILES, 256>>>(U2);
        k_finalize<<<1, 64>>>(ug2 + l * 64, ube2 + l * 64, invN);
        k_node_upd<<<3125, 256>>>();
    }
    k_pred<<<(NN + 7) / 8, 256>>>(pW, pb, out);
    (void)in_sizes; (void)n_in; (void)out_size;
}